// round 10
// baseline (speedup 1.0000x reference)
#include <cuda_runtime.h>
#include <cstdint>

#define N_ROWS 2048
#define W_FLAT (128*128*3)
#define MAX_TILES 256

// ---------------- tile list ----------------
__device__ int g_t_p0[MAX_TILES];
__device__ int g_t_pcnt[MAX_TILES];
__device__ int g_t_seg[MAX_TILES];
__device__ int g_t_irr[MAX_TILES];
__device__ int g_ntiles;

__global__ void build_tiles_kernel(const int* __restrict__ repeats) {
    int t = threadIdx.x;          // 0..31
    int cnt = repeats[t];
    int inc = cnt;
    #pragma unroll
    for (int off = 1; off < 32; off <<= 1) {
        int v = __shfl_up_sync(0xFFFFFFFFu, inc, off);
        if (t >= off) inc += v;
    }
    int start = inc - cnt;        // segment start row

    const int Ds[3] = {5, 3, 1};  // heavy irreps first
    int base = 0;
    #pragma unroll
    for (int ir = 0; ir < 3; ir++) {
        int D = Ds[ir];
        int pc = cnt * D;
        int nt = (pc + 127) >> 7;
        int ti = nt;
        #pragma unroll
        for (int off = 1; off < 32; off <<= 1) {
            int v = __shfl_up_sync(0xFFFFFFFFu, ti, off);
            if (t >= off) ti += v;
        }
        int ts = ti - nt;
        for (int k = 0; k < nt; k++) {
            int idx = base + ts + k;
            g_t_p0[idx]   = start * D + k * 128;
            int rem = pc - k * 128;
            g_t_pcnt[idx] = rem < 128 ? rem : 128;
            g_t_seg[idx]  = t;
            g_t_irr[idx]  = ir;
        }
        base += __shfl_sync(0xFFFFFFFFu, ti, 31);
    }
    if (t == 0) g_ntiles = base;
}

// ---------------- helpers ----------------
__device__ __forceinline__ void tf32_split(float v, uint32_t& hb, uint32_t& lb) {
    asm("cvt.rna.tf32.f32 %0, %1;" : "=r"(hb) : "f"(v));
    float lf = v - __uint_as_float(hb);
    asm("cvt.rna.tf32.f32 %0, %1;" : "=r"(lb) : "f"(lf));
}
__device__ __forceinline__ void mma8(float* d, uint32_t a0, uint32_t a1,
                                     uint32_t a2, uint32_t a3,
                                     uint32_t b0, uint32_t b1) {
    asm("mma.sync.aligned.m16n8k8.row.col.f32.tf32.tf32.f32 "
        "{%0,%1,%2,%3}, {%4,%5,%6,%7}, {%8,%9}, {%0,%1,%2,%3};"
        : "+f"(d[0]), "+f"(d[1]), "+f"(d[2]), "+f"(d[3])
        : "r"(a0), "r"(a1), "r"(a2), "r"(a3), "r"(b0), "r"(b1));
}

// smem (float4 units): AH 1024 | AL 1024 | BH 1024 | BL 1024  = 64 KB
#define SM_AH 0
#define SM_AL 1024
#define SM_BH 2048
#define SM_BL 3072
#define SMEM_BYTES (4096 * 16)

// ---------------------------------------------------------------------------
// One 128-row tile: Y2d[p,o] = alpha * sum_m X2d[p,m] * W[g][m,o]
// X2d[p,m] = x[(n*128+m)*D + i], p = n*D + i.
// tf32 3-term emulation on mma.sync.m16n8k8. Operands staged in smem in
// fragment order (conflict-free LDS.128 per operand fetch).
// Block = 256 thr = 8 warps (wr 0..3 x wc 0..1); warp tile 32 x 64.
// ---------------------------------------------------------------------------
template <int D>
__device__ __forceinline__ void body(const float* __restrict__ x,
                                     const float* __restrict__ w,
                                     float* __restrict__ out,
                                     int woff, float4* sm4,
                                     int p0, int pcnt, int g) {
    const int tid  = threadIdx.x;
    const int wid  = tid >> 5;
    const int lane = tid & 31;
    const int wr   = wid & 3;      // warp row group (32 rows)
    const int wc   = wid >> 2;     // warp col group (64 cols)

    const float* __restrict__ wg = w + (size_t)g * W_FLAT + woff;

    float acc[64];                 // [mt][nt][reg] = [2][8][4]
    #pragma unroll
    for (int i = 0; i < 64; i++) acc[i] = 0.0f;

    for (int c = 0; c < 4; c++) {
        const int mc = c * 32;
        if (c) __syncthreads();    // previous chunk's compute done

        // ---- stage A (X rows, tf32 hi/lo, fragment order) ----
        #pragma unroll
        for (int it = 0; it < 16; it++) {
            int idx = tid + it * 256;
            int k = idx & 31;          // k within chunk
            int r = idx >> 5;          // p-row 0..127
            float v = 0.0f;
            if (r < pcnt) {
                int p = p0 + r;
                int n = p / D;
                int i = p - n * D;
                v = x[((size_t)n * 128 + (mc + k)) * D + i];
            }
            uint32_t hb, lb;
            tf32_split(v, hb, lb);
            int ks = k >> 3, kk = k & 7;
            int awr = r >> 5, mt = (r >> 4) & 1, rm = r & 15;
            int fl  = (rm & 7) * 4 + (kk & 3);
            int reg = ((rm >> 3) & 1) | ((kk >> 2) << 1);
            int fidx = (((awr * 4 + ks) * 2 + mt) * 32 + fl);
            ((uint32_t*)&sm4[SM_AH + fidx])[reg] = hb;
            ((uint32_t*)&sm4[SM_AL + fidx])[reg] = lb;
        }

        // ---- stage B (W^T: B[o][k] = w[m][o], fragment order) ----
        #pragma unroll
        for (int it = 0; it < 16; it++) {
            int idx = tid + it * 256;
            int o = idx & 127;
            int k = idx >> 7;
            float v = wg[(size_t)(mc + k) * 128 + o];
            uint32_t hb, lb;
            tf32_split(v, hb, lb);
            int ks = k >> 3, kk = k & 7;
            int bwc = o >> 6, nt = (o >> 3) & 7, n8 = o & 7;
            int fl   = n8 * 4 + (kk & 3);
            int reg  = (kk >> 2) & 1;
            int comp = (nt & 1) * 2 + reg;
            int fidx = (((bwc * 4 + ks) * 4 + (nt >> 1)) * 32 + fl);
            ((uint32_t*)&sm4[SM_BH + fidx])[comp] = hb;
            ((uint32_t*)&sm4[SM_BL + fidx])[comp] = lb;
        }
        __syncthreads();

        // ---- compute: 4 k-steps, 48 mma each ----
        #pragma unroll
        for (int ks = 0; ks < 4; ks++) {
            const float4* pa  = sm4 + SM_AH + ((wr * 4 + ks) * 2) * 32 + lane;
            const float4* pal = sm4 + SM_AL + ((wr * 4 + ks) * 2) * 32 + lane;
            const float4* pb  = sm4 + SM_BH + ((wc * 4 + ks) * 4) * 32 + lane;
            const float4* pbl = sm4 + SM_BL + ((wc * 4 + ks) * 4) * 32 + lane;

            float4 ah[2] = {pa[0], pa[32]};
            float4 al[2] = {pal[0], pal[32]};
            float4 bh[4] = {pb[0], pb[32], pb[64], pb[96]};
            float4 bl[4] = {pbl[0], pbl[32], pbl[64], pbl[96]};

            #pragma unroll
            for (int mt = 0; mt < 2; mt++) {
                uint32_t ah0 = __float_as_uint(ah[mt].x), ah1 = __float_as_uint(ah[mt].y);
                uint32_t ah2 = __float_as_uint(ah[mt].z), ah3 = __float_as_uint(ah[mt].w);
                uint32_t al0 = __float_as_uint(al[mt].x), al1 = __float_as_uint(al[mt].y);
                uint32_t al2 = __float_as_uint(al[mt].z), al3 = __float_as_uint(al[mt].w);
                #pragma unroll
                for (int np = 0; np < 4; np++) {
                    uint32_t be0 = __float_as_uint(bh[np].x), be1 = __float_as_uint(bh[np].y);
                    uint32_t bo0 = __float_as_uint(bh[np].z), bo1 = __float_as_uint(bh[np].w);
                    uint32_t ble0 = __float_as_uint(bl[np].x), ble1 = __float_as_uint(bl[np].y);
                    uint32_t blo0 = __float_as_uint(bl[np].z), blo1 = __float_as_uint(bl[np].w);
                    float* d0 = acc + mt * 32 + (2 * np) * 4;
                    float* d1 = acc + mt * 32 + (2 * np + 1) * 4;
                    // hi*hi
                    mma8(d0, ah0, ah1, ah2, ah3, be0, be1);
                    mma8(d1, ah0, ah1, ah2, ah3, bo0, bo1);
                    // lo*hi
                    mma8(d0, al0, al1, al2, al3, be0, be1);
                    mma8(d1, al0, al1, al2, al3, bo0, bo1);
                    // hi*lo
                    mma8(d0, ah0, ah1, ah2, ah3, ble0, ble1);
                    mma8(d1, ah0, ah1, ah2, ah3, blo0, blo1);
                }
            }
        }
    }

    // ---- epilogue: direct register -> gmem ----
    const float alpha = 0.015625f;   // 1/sqrt(32*128)
    #pragma unroll
    for (int mt = 0; mt < 2; mt++) {
        #pragma unroll
        for (int h = 0; h < 2; h++) {
            int row = wr * 32 + mt * 16 + (lane >> 2) + h * 8;
            if (row < pcnt) {
                int p = p0 + row;
                int n = p / D;
                int i = p - n * D;
                float* ob = out + (size_t)n * 128 * D + i;
                #pragma unroll
                for (int nt = 0; nt < 8; nt++) {
                    int o = wc * 64 + nt * 8 + (lane & 3) * 2;
                    float v0 = acc[mt * 32 + nt * 4 + h * 2 + 0];
                    float v1 = acc[mt * 32 + nt * 4 + h * 2 + 1];
                    ob[(size_t)o * D]       = v0 * alpha;
                    ob[(size_t)(o + 1) * D] = v1 * alpha;
                }
            }
        }
    }
}

// ---------------------------------------------------------------------------
__global__ __launch_bounds__(256)
void irreps_mma_kernel(const float* __restrict__ x0,
                       const float* __restrict__ x1,
                       const float* __restrict__ x2,
                       const float* __restrict__ w,
                       float* __restrict__ out) {
    extern __shared__ float4 sm4[];
    int tile = blockIdx.x;
    if (tile >= g_ntiles) return;

    const int p0   = g_t_p0[tile];
    const int pcnt = g_t_pcnt[tile];
    const int g    = g_t_seg[tile];
    const int ir   = g_t_irr[tile];

    const size_t y0 = (size_t)N_ROWS * 128 * 1;
    const size_t y1 = (size_t)N_ROWS * 128 * 3;

    if (ir == 0)
        body<5>(x2, w, out + y0 + y1, 2 * 128 * 128, sm4, p0, pcnt, g);
    else if (ir == 1)
        body<3>(x1, w, out + y0, 128 * 128, sm4, p0, pcnt, g);
    else
        body<1>(x0, w, out, 0, sm4, p0, pcnt, g);
}

// ---------------------------------------------------------------------------
extern "C" void kernel_launch(void* const* d_in, const int* in_sizes, int n_in,
                              void* d_out, int out_size) {
    const float* x0 = (const float*)d_in[0];   // (2048,128,1)
    const float* x1 = (const float*)d_in[1];   // (2048,128,3)
    const float* x2 = (const float*)d_in[2];   // (2048,128,5)
    const float* w  = (const float*)d_in[3];   // (32, 49152)
    const int*   rp = (const int*)d_in[4];     // (32,)
    float* out = (float*)d_out;

    cudaFuncSetAttribute(irreps_mma_kernel,
                         cudaFuncAttributeMaxDynamicSharedMemorySize, SMEM_BYTES);

    build_tiles_kernel<<<1, 32>>>(rp);
    irreps_mma_kernel<<<MAX_TILES, 256, SMEM_BYTES>>>(x0, x1, x2, w, out);
}